// round 15
// baseline (speedup 1.0000x reference)
#include <cuda_runtime.h>
#include <cuda_bf16.h>
#include <cuda_fp16.h>
#include <cstdint>

// Problem constants (AttentionPool: N=262144, D=512, H=128, B=1024)
#define MAXN 262144
#define MAXB 4096
#define DIM 512
#define HID 128

// ---------------------------------------------------------------------------
// Scratch (allocation-free rule: __device__ globals)
// ---------------------------------------------------------------------------
__device__ __align__(16) float g_num[(size_t)MAXB * DIM];   // 8 MB
__device__ float g_den[MAXB];
// W1^T as fp16, layout [n][k]: n=0..127 rows, k=0..511 contiguous
__device__ __align__(16) unsigned short g_w1t[HID * DIM];
// x as fp16, written by the GEMM phase, pooled from L2 shortly after (256 MB)
__device__ __align__(16) unsigned short g_xf16[(size_t)MAXN * DIM];

// ---------------------------------------------------------------------------
// Kernel 0 (fused prep):
//  blocks 0..3  : W1^T fp16 transpose via smem (coalesced both sides)
//  blocks 4..131: zero g_num[0..Bseg*DIM) and g_den[0..Bseg)
// ---------------------------------------------------------------------------
#define TPAD 132   // halfs per smem tile row
#define ZBLK 128

__global__ __launch_bounds__(256)
void prep_kernel(int Bseg, const float* __restrict__ W1)
{
    __shared__ unsigned short tile[128][TPAD];
    const int tid = threadIdx.x;

    if (blockIdx.x < 4) {
        const int k0 = blockIdx.x * 128;
#pragma unroll
        for (int u = 0; u < 16; u++) {
            int idx = tid + u * 256;
            int kr = idx >> 5;
            int c4 = idx & 31;
            float4 v = __ldg(reinterpret_cast<const float4*>(
                W1 + (size_t)(k0 + kr) * HID + c4 * 4));
            tile[c4 * 4 + 0][kr] = __half_as_ushort(__float2half_rn(v.x));
            tile[c4 * 4 + 1][kr] = __half_as_ushort(__float2half_rn(v.y));
            tile[c4 * 4 + 2][kr] = __half_as_ushort(__float2half_rn(v.z));
            tile[c4 * 4 + 3][kr] = __half_as_ushort(__float2half_rn(v.w));
        }
        __syncthreads();
#pragma unroll
        for (int u = 0; u < 8; u++) {
            int idx = tid + u * 256;
            int nn = idx >> 4;
            int c8 = idx & 15;
            unsigned short h[8];
#pragma unroll
            for (int j = 0; j < 8; j++) h[j] = tile[nn][c8 * 8 + j];
            *reinterpret_cast<uint4*>(g_w1t + (size_t)nn * DIM + k0 + c8 * 8) =
                *reinterpret_cast<const uint4*>(h);
        }
        return;
    }

    // --- zero accumulators
    const int gid = (blockIdx.x - 4) * 256 + tid;     // ZBLK*256 threads
    const int tot4 = Bseg * (DIM / 4);                // float4 count
    const uint4 z = make_uint4(0, 0, 0, 0);
    for (int i = gid; i < tot4; i += ZBLK * 256)
        reinterpret_cast<uint4*>(g_num)[i] = z;
    if (gid < Bseg) g_den[gid] = 0.f;
}

// ---------------------------------------------------------------------------
// PTX helpers (all sm_80+ baseline -> safe for compute_103 target)
// ---------------------------------------------------------------------------
__device__ __forceinline__ void mma_f16(float* d, const uint32_t* a, const uint32_t* b)
{
    asm volatile(
        "mma.sync.aligned.m16n8k16.row.col.f32.f16.f16.f32 "
        "{%0,%1,%2,%3}, {%4,%5,%6,%7}, {%8,%9}, {%0,%1,%2,%3};"
        : "+f"(d[0]), "+f"(d[1]), "+f"(d[2]), "+f"(d[3])
        : "r"(a[0]), "r"(a[1]), "r"(a[2]), "r"(a[3]), "r"(b[0]), "r"(b[1]));
}
__device__ __forceinline__ void ldsm_x4(uint32_t* r, uint32_t addr)
{
    asm volatile("ldmatrix.sync.aligned.m8n8.x4.shared.b16 {%0,%1,%2,%3}, [%4];"
                 : "=r"(r[0]), "=r"(r[1]), "=r"(r[2]), "=r"(r[3]) : "r"(addr));
}
__device__ __forceinline__ void cp16(uint32_t dst, const void* src)
{
    asm volatile("cp.async.cg.shared.global [%0], [%1], 16;"
                 :: "r"(dst), "l"(src) : "memory");
}
__device__ __forceinline__ void cp_commit()
{
    asm volatile("cp.async.commit_group;" ::: "memory");
}
template <int N>
__device__ __forceinline__ void cp_wait()
{
    asm volatile("cp.async.wait_group %0;" :: "n"(N) : "memory");
}
__device__ __forceinline__ uint32_t smem_u32(const void* p)
{
    uint32_t a;
    asm("{ .reg .u64 t; cvta.to.shared.u64 t, %1; cvt.u32.u64 %0, t; }" : "=r"(a) : "l"(p));
    return a;
}

// ---------------------------------------------------------------------------
// Kernel 1 (fused score + scatter-pool), 128-row frame (R8-measured GEMM):
//   s = tanh(x @ W1 + b1) @ W2 + b2     (single-pass fp16 mma)
// GEMM phase also writes x as fp16 to g_xf16 (free: latency-bound regime,
// per R8 measurement). Pool phase re-reads the fp16 tile (L2-hot, half the
// bytes of fp32) and scatters num[seg] += e_i * x_i, den[seg] += e_i.
// Block: 128 rows x 128 cols, 8 warps 4x2 (warp tile 32x64), K: 8 tiles of 64.
// ---------------------------------------------------------------------------
#define KT       64
#define ROWPADB  144                      // bytes per smem row
#define TILE_B   (128 * ROWPADB)          // 18432 bytes per tile buffer
#define OFF_A    0
#define OFF_B0   (1 * TILE_B)
#define OFF_B1   (2 * TILE_B)
#define OFF_TAIL (3 * TILE_B)
// tail: seg[128] ints | e[128] floats | red[128*2] floats
#define OFF_SEG  OFF_TAIL
#define OFF_E    (OFF_TAIL + 512)
#define OFF_RED  (OFF_TAIL + 1024)
#define SMEM_REQ (OFF_TAIL + 2048)        // 57344 B

__global__ __launch_bounds__(256, 2)
void score_pool_kernel(const float* __restrict__ x,
                       const void* __restrict__ batch, int n,
                       const float* __restrict__ b1,
                       const float* __restrict__ W2,
                       const float* __restrict__ b2)
{
    extern __shared__ char bp[];
    const uint32_t sbase = smem_u32(bp);

    const int tid = threadIdx.x;
    const int wid = tid >> 5;
    const int lid = tid & 31;
    const int tig = lid & 3;             // 0..3
    const int warp_row = wid & 3;        // rows warp_row*32 ..
    const int warp_col = wid >> 2;       // cols warp_col*64 ..
    const int rowBase = blockIdx.x * 128;

    int*   seg_sm = (int*)(bp + OFF_SEG);
    float* e_sm   = (float*)(bp + OFF_E);
    float* red    = (float*)(bp + OFF_RED);

    // --- load segment ids for this block's rows
    if (tid < 128) {
        const int i32 = (__ldg((const int*)batch + (n - 1)) != 0);
        seg_sm[tid] = i32 ? __ldg((const int*)batch + rowBase + tid)
                          : (int)__ldg((const long long*)batch + rowBase + tid);
    }

    // ldmatrix per-lane addresses
    const uint32_t a_rl    = (uint32_t)(lid & 15);
    const uint32_t a_chalf = (uint32_t)((lid >> 4) * 16);
    uint32_t aA[2];
#pragma unroll
    for (int m = 0; m < 2; m++) {
        uint32_t row = (uint32_t)(warp_row * 32 + m * 16) + a_rl;
        aA[m] = sbase + OFF_A + row * ROWPADB + a_chalf;
    }
    const uint32_t b_lane = ((uint32_t)(lid & 7) + (uint32_t)((lid >> 4) & 1) * 8) * ROWPADB
                          + (uint32_t)((lid >> 3) & 1) * 16
                          + (uint32_t)warp_col * 64 * ROWPADB;

    float acc[2][8][4];
#pragma unroll
    for (int m = 0; m < 2; m++)
#pragma unroll
        for (int nt = 0; nt < 8; nt++)
#pragma unroll
            for (int j = 0; j < 4; j++) acc[m][nt][j] = 0.f;

    // --- prologue: B[0] via cp.async; A[0] LDGs into registers
    {
#pragma unroll
        for (int u = 0; u < 4; u++) {
            int idx = tid + u * 256;
            int nn = idx >> 3, c8 = idx & 7;
            uint32_t doff = (uint32_t)nn * ROWPADB + (uint32_t)c8 * 16;
            uint32_t goff = (uint32_t)nn * DIM + (uint32_t)c8 * 8;  // t=0
            cp16(sbase + OFF_B0 + doff, g_w1t + goff);
        }
        cp_commit();
    }
    float4 va[8];
#pragma unroll
    for (int u = 0; u < 4; u++) {
        int idx = tid + u * 256;
        int r = idx >> 3, c8 = idx & 7;
        const float4* src = reinterpret_cast<const float4*>(
            x + (size_t)(rowBase + r) * DIM + c8 * 8);
        va[2 * u]     = __ldg(src);
        va[2 * u + 1] = __ldg(src + 1);
    }

    for (int t = 0; t < 8; t++) {
        if (t > 0) __syncthreads();      // prior tile reads done before overwrite

        // --- convert prefetched A (fp32 -> fp16): smem + fp16 side copy
#pragma unroll
        for (int u = 0; u < 4; u++) {
            int idx = tid + u * 256;
            int r = idx >> 3, c8 = idx & 7;
            float f[8] = {va[2 * u].x, va[2 * u].y, va[2 * u].z, va[2 * u].w,
                          va[2 * u + 1].x, va[2 * u + 1].y, va[2 * u + 1].z, va[2 * u + 1].w};
            uint32_t hp[4];
#pragma unroll
            for (int j = 0; j < 4; j++) {
                __half h0 = __float2half_rn(f[2 * j]);
                __half h1 = __float2half_rn(f[2 * j + 1]);
                hp[j] = (uint32_t)__half_as_ushort(h0) | ((uint32_t)__half_as_ushort(h1) << 16);
            }
            uint32_t off = (uint32_t)r * ROWPADB + (uint32_t)c8 * 16;
            uint4 v = make_uint4(hp[0], hp[1], hp[2], hp[3]);
            *(uint4*)(bp + OFF_A + off) = v;
            *reinterpret_cast<uint4*>(g_xf16 +
                (size_t)(rowBase + r) * DIM + t * KT + c8 * 8) = v;
        }

        // --- issue B[t+1] cp.async into alternate buffer, wait for B[t]
        if (t < 7) {
            uint32_t bufo = ((t + 1) & 1) ? OFF_B1 : OFF_B0;
#pragma unroll
            for (int u = 0; u < 4; u++) {
                int idx = tid + u * 256;
                int nn = idx >> 3, c8 = idx & 7;
                uint32_t doff = (uint32_t)nn * ROWPADB + (uint32_t)c8 * 16;
                uint32_t goff = (uint32_t)nn * DIM + (uint32_t)(t + 1) * KT + (uint32_t)c8 * 8;
                cp16(sbase + bufo + doff, g_w1t + goff);
            }
            cp_commit();
            cp_wait<1>();                 // B[t] complete; B[t+1] may stay in flight
        } else {
            cp_wait<0>();
        }
        __syncthreads();

        // --- prefetch next A tile LDGs (latency hidden behind compute below)
        if (t < 7) {
#pragma unroll
            for (int u = 0; u < 4; u++) {
                int idx = tid + u * 256;
                int r = idx >> 3, c8 = idx & 7;
                const float4* src = reinterpret_cast<const float4*>(
                    x + (size_t)(rowBase + r) * DIM + (t + 1) * KT + c8 * 8);
                va[2 * u]     = __ldg(src);
                va[2 * u + 1] = __ldg(src + 1);
            }
        }

        // --- compute: 4 k-steps of 16, single pass
        const uint32_t bA = sbase + ((t & 1) ? OFF_B1 : OFF_B0) + b_lane;
#pragma unroll
        for (int ks = 0; ks < 4; ks++) {
            const uint32_t ko = (uint32_t)ks * 32;
            uint32_t a[2][4];
#pragma unroll
            for (int m = 0; m < 2; m++) ldsm_x4(a[m], aA[m] + ko);
#pragma unroll
            for (int ntp = 0; ntp < 4; ntp++) {
                const uint32_t no = (uint32_t)ntp * 16 * ROWPADB + ko;
                uint32_t bh[4];
                ldsm_x4(bh, bA + no);
#pragma unroll
                for (int m = 0; m < 2; m++) {
                    mma_f16(acc[m][2 * ntp],     a[m], bh);
                    mma_f16(acc[m][2 * ntp + 1], a[m], bh + 2);
                }
            }
        }
    }

    // --- epilogue: s = sum_col tanh(h + b1[col]) * W2[col], register-resident
    const int grp = lid >> 2;
    float p[2][2] = {{0.f, 0.f}, {0.f, 0.f}};
#pragma unroll
    for (int nt = 0; nt < 8; nt++) {
        int c0 = warp_col * 64 + nt * 8 + tig * 2;
        float b1a = __ldg(b1 + c0),     b1b = __ldg(b1 + c0 + 1);
        float w2a = __ldg(W2 + c0),     w2b = __ldg(W2 + c0 + 1);
#pragma unroll
        for (int m = 0; m < 2; m++) {
            p[m][0] += tanhf(acc[m][nt][0] + b1a) * w2a + tanhf(acc[m][nt][1] + b1b) * w2b;
            p[m][1] += tanhf(acc[m][nt][2] + b1a) * w2a + tanhf(acc[m][nt][3] + b1b) * w2b;
        }
    }
#pragma unroll
    for (int m = 0; m < 2; m++)
#pragma unroll
        for (int r = 0; r < 2; r++) {
            p[m][r] += __shfl_xor_sync(0xFFFFFFFF, p[m][r], 1);
            p[m][r] += __shfl_xor_sync(0xFFFFFFFF, p[m][r], 2);
        }
    if (tig == 0) {
#pragma unroll
        for (int m = 0; m < 2; m++)
#pragma unroll
            for (int r = 0; r < 2; r++) {
                int row = warp_row * 32 + m * 16 + r * 8 + grp;
                red[row * 2 + warp_col] = p[m][r];
            }
    }
    __syncthreads();
    if (tid < 128) {
        float s = red[tid * 2] + red[tid * 2 + 1] + __ldg(b2);
        e_sm[tid] = expf(s);             // no shift needed: |s| <= ~10, fp32-safe
    }
    __syncthreads();                     // also makes g_xf16 writes block-visible

    // --- scatter-pool: re-read this block's fp16 tile (L2-hot, half bytes).
    // 2 row-parity groups x 128 col-chunks; thread owns dims 4*ct..4*ct+3.
    {
        const int group = tid >> 7;      // 0: even rows, 1: odd rows
        const int ct = tid & 127;        // 4-half chunk within row
        const uint2* xp = reinterpret_cast<const uint2*>(
            g_xf16 + (size_t)rowBase * DIM) + ct;    // + r*(DIM/4) per row
        float a0 = 0.f, a1 = 0.f, a2 = 0.f, a3 = 0.f;
        int cur = seg_sm[group];
        for (int r0 = group; r0 < 128; r0 += 8) {
            uint2 v[4];
#pragma unroll
            for (int j = 0; j < 4; j++)
                v[j] = __ldg(xp + (size_t)(r0 + 2 * j) * (DIM / 4));
#pragma unroll
            for (int j = 0; j < 4; j++) {
                int r = r0 + 2 * j;
                int sg = seg_sm[r];
                if (sg != cur) {
                    atomicAdd(&g_num[(size_t)cur * DIM + 4 * ct + 0], a0);
                    atomicAdd(&g_num[(size_t)cur * DIM + 4 * ct + 1], a1);
                    atomicAdd(&g_num[(size_t)cur * DIM + 4 * ct + 2], a2);
                    atomicAdd(&g_num[(size_t)cur * DIM + 4 * ct + 3], a3);
                    a0 = a1 = a2 = a3 = 0.f; cur = sg;
                }
                float e = e_sm[r];
                float2 f0 = __half22float2(*reinterpret_cast<const __half2*>(&v[j].x));
                float2 f1 = __half22float2(*reinterpret_cast<const __half2*>(&v[j].y));
                a0 += e * f0.x; a1 += e * f0.y;
                a2 += e * f1.x; a3 += e * f1.y;
            }
        }
        atomicAdd(&g_num[(size_t)cur * DIM + 4 * ct + 0], a0);
        atomicAdd(&g_num[(size_t)cur * DIM + 4 * ct + 1], a1);
        atomicAdd(&g_num[(size_t)cur * DIM + 4 * ct + 2], a2);
        atomicAdd(&g_num[(size_t)cur * DIM + 4 * ct + 3], a3);
    }
    if (tid == 0) {
        float d = 0.f;
        int cur = seg_sm[0];
        for (int r = 0; r < 128; r++) {
            int sg = seg_sm[r];
            if (sg != cur) { atomicAdd(&g_den[cur], d); d = 0.f; cur = sg; }
            d += e_sm[r];
        }
        atomicAdd(&g_den[cur], d);
    }
}

// ---------------------------------------------------------------------------
// Kernel 2 (finalize): out[b, d] = num[b, d] / (den[b] + 1e-8)
// ---------------------------------------------------------------------------
__global__ __launch_bounds__(256)
void finalize_kernel(float* __restrict__ out)
{
    const int b = blockIdx.x;
    const int tid = threadIdx.x;
    const float inv = 1.f / (g_den[b] + 1e-8f);
    float2 v = reinterpret_cast<const float2*>(g_num + (size_t)b * DIM)[tid];
    reinterpret_cast<float2*>(out + (size_t)b * DIM)[tid] =
        make_float2(v.x * inv, v.y * inv);
}

// ---------------------------------------------------------------------------
extern "C" void kernel_launch(void* const* d_in, const int* in_sizes, int n_in,
                              void* d_out, int out_size)
{
    const float* x     = (const float*)d_in[0];
    const void*  batch = (const void*)d_in[1];
    const float* W1    = (const float*)d_in[2];
    const float* b1    = (const float*)d_in[3];
    const float* W2    = (const float*)d_in[4];
    const float* b2    = (const float*)d_in[5];
    float*       out   = (float*)d_out;

    const int n = in_sizes[1];
    const int Bseg = out_size / DIM;

    cudaFuncSetAttribute(score_pool_kernel,
                         cudaFuncAttributeMaxDynamicSharedMemorySize, SMEM_REQ);

    prep_kernel<<<4 + ZBLK, 256>>>(Bseg, W1);
    score_pool_kernel<<<n / 128, 256, SMEM_REQ>>>(x, batch, n, b1, W2, b2);
    finalize_kernel<<<Bseg, 256>>>(out);
}

// round 17
// speedup vs baseline: 1.1425x; 1.1425x over previous
#include <cuda_runtime.h>
#include <cuda_bf16.h>
#include <cuda_fp16.h>
#include <cstdint>

// Problem constants (AttentionPool: N=262144, D=512, H=128, B=1024)
#define MAXN 262144
#define MAXB 4096
#define DIM 512
#define HID 128

// ---------------------------------------------------------------------------
// Scratch (allocation-free rule: __device__ globals)
// ---------------------------------------------------------------------------
__device__ __align__(16) float g_num[(size_t)MAXB * DIM];   // 8 MB
__device__ float g_den[MAXB];
// W1^T as fp16, layout [n][k]: n=0..127 rows, k=0..511 contiguous
__device__ __align__(16) unsigned short g_w1t[HID * DIM];

// ---------------------------------------------------------------------------
// Kernel 0 (fused prep):
//  blocks 0..3  : W1^T fp16 transpose via smem (coalesced both sides)
//  blocks 4..131: zero g_num[0..Bseg*DIM) and g_den[0..Bseg)
// ---------------------------------------------------------------------------
#define TPAD 132   // halfs per smem tile row
#define ZBLK 128

__global__ __launch_bounds__(256)
void prep_kernel(int Bseg, const float* __restrict__ W1)
{
    __shared__ unsigned short tile[128][TPAD];
    const int tid = threadIdx.x;

    if (blockIdx.x < 4) {
        const int k0 = blockIdx.x * 128;
#pragma unroll
        for (int u = 0; u < 16; u++) {
            int idx = tid + u * 256;
            int kr = idx >> 5;
            int c4 = idx & 31;
            float4 v = __ldg(reinterpret_cast<const float4*>(
                W1 + (size_t)(k0 + kr) * HID + c4 * 4));
            tile[c4 * 4 + 0][kr] = __half_as_ushort(__float2half_rn(v.x));
            tile[c4 * 4 + 1][kr] = __half_as_ushort(__float2half_rn(v.y));
            tile[c4 * 4 + 2][kr] = __half_as_ushort(__float2half_rn(v.z));
            tile[c4 * 4 + 3][kr] = __half_as_ushort(__float2half_rn(v.w));
        }
        __syncthreads();
#pragma unroll
        for (int u = 0; u < 8; u++) {
            int idx = tid + u * 256;
            int nn = idx >> 4;
            int c8 = idx & 15;
            unsigned short h[8];
#pragma unroll
            for (int j = 0; j < 8; j++) h[j] = tile[nn][c8 * 8 + j];
            *reinterpret_cast<uint4*>(g_w1t + (size_t)nn * DIM + k0 + c8 * 8) =
                *reinterpret_cast<const uint4*>(h);
        }
        return;
    }

    // --- zero accumulators
    const int gid = (blockIdx.x - 4) * 256 + tid;     // ZBLK*256 threads
    const int tot4 = Bseg * (DIM / 4);                // float4 count
    const uint4 z = make_uint4(0, 0, 0, 0);
    for (int i = gid; i < tot4; i += ZBLK * 256)
        reinterpret_cast<uint4*>(g_num)[i] = z;
    if (gid < Bseg) g_den[gid] = 0.f;
}

// ---------------------------------------------------------------------------
// PTX helpers (all sm_80+ baseline -> safe for compute_103 target)
// ---------------------------------------------------------------------------
__device__ __forceinline__ void mma_f16(float* d, const uint32_t* a, const uint32_t* b)
{
    asm volatile(
        "mma.sync.aligned.m16n8k16.row.col.f32.f16.f16.f32 "
        "{%0,%1,%2,%3}, {%4,%5,%6,%7}, {%8,%9}, {%0,%1,%2,%3};"
        : "+f"(d[0]), "+f"(d[1]), "+f"(d[2]), "+f"(d[3])
        : "r"(a[0]), "r"(a[1]), "r"(a[2]), "r"(a[3]), "r"(b[0]), "r"(b[1]));
}
__device__ __forceinline__ void ldsm_x4(uint32_t* r, uint32_t addr)
{
    asm volatile("ldmatrix.sync.aligned.m8n8.x4.shared.b16 {%0,%1,%2,%3}, [%4];"
                 : "=r"(r[0]), "=r"(r[1]), "=r"(r[2]), "=r"(r[3]) : "r"(addr));
}
__device__ __forceinline__ void cp16(uint32_t dst, const void* src)
{
    asm volatile("cp.async.cg.shared.global [%0], [%1], 16;"
                 :: "r"(dst), "l"(src) : "memory");
}
__device__ __forceinline__ void cp_commit()
{
    asm volatile("cp.async.commit_group;" ::: "memory");
}
template <int N>
__device__ __forceinline__ void cp_wait()
{
    asm volatile("cp.async.wait_group %0;" :: "n"(N) : "memory");
}
__device__ __forceinline__ uint32_t smem_u32(const void* p)
{
    uint32_t a;
    asm("{ .reg .u64 t; cvta.to.shared.u64 t, %1; cvt.u32.u64 %0, t; }" : "=r"(a) : "l"(p));
    return a;
}

// ---------------------------------------------------------------------------
// Kernel 1 (fused score + scatter-pool), 128-row frame:
//   s = tanh(x @ W1 + b1) @ W2 + b2     (single-pass fp16 mma)
// then e_i = exp(s_i) and the block RE-READS its own x tile (fp32, L2-hot,
// evict-first) to scatter num[seg] += e_i * x_i, den[seg] += e_i.
// ONE barrier per k-tile, made safe by A double-buffer + B TRIPLE-buffer:
// every smem WAR hazard crosses at least one __syncthreads (B(t+1) writes
// buf (t+1)%3 whose last reader was compute(t-2), which precedes barrier(t-1),
// which precedes this iteration's cp.async issue in all warps).
// Block: 128 rows x 128 cols, 8 warps 4x2 (warp tile 32x64), K: 8 tiles of 64.
// ---------------------------------------------------------------------------
#define KT       64
#define ROWPADB  144                      // bytes per smem row
#define TILE_B   (128 * ROWPADB)          // 18432 bytes per tile buffer
#define OFF_A0   0
#define OFF_A1   (1 * TILE_B)
#define OFF_B    (2 * TILE_B)             // 3 buffers: OFF_B + b*TILE_B
#define OFF_TAIL (5 * TILE_B)
// tail: seg[128] ints | e[128] floats | red[128*2] floats
#define OFF_SEG  OFF_TAIL
#define OFF_E    (OFF_TAIL + 512)
#define OFF_RED  (OFF_TAIL + 1024)
#define SMEM_REQ (OFF_TAIL + 2048)        // 94208 B

__global__ __launch_bounds__(256, 2)
void score_pool_kernel(const float* __restrict__ x,
                       const void* __restrict__ batch, int n,
                       const float* __restrict__ b1,
                       const float* __restrict__ W2,
                       const float* __restrict__ b2)
{
    extern __shared__ char bp[];
    const uint32_t sbase = smem_u32(bp);

    const int tid = threadIdx.x;
    const int wid = tid >> 5;
    const int lid = tid & 31;
    const int tig = lid & 3;             // 0..3
    const int warp_row = wid & 3;        // rows warp_row*32 ..
    const int warp_col = wid >> 2;       // cols warp_col*64 ..
    const int rowBase = blockIdx.x * 128;

    int*   seg_sm = (int*)(bp + OFF_SEG);
    float* e_sm   = (float*)(bp + OFF_E);
    float* red    = (float*)(bp + OFF_RED);

    // --- load segment ids for this block's rows
    if (tid < 128) {
        const int i32 = (__ldg((const int*)batch + (n - 1)) != 0);
        seg_sm[tid] = i32 ? __ldg((const int*)batch + rowBase + tid)
                          : (int)__ldg((const long long*)batch + rowBase + tid);
    }

    // ldmatrix per-lane addresses (A base; add buffer offset per tile)
    const uint32_t a_rl    = (uint32_t)(lid & 15);
    const uint32_t a_chalf = (uint32_t)((lid >> 4) * 16);
    uint32_t aA[2];
#pragma unroll
    for (int m = 0; m < 2; m++) {
        uint32_t row = (uint32_t)(warp_row * 32 + m * 16) + a_rl;
        aA[m] = sbase + OFF_A0 + row * ROWPADB + a_chalf;
    }
    const uint32_t b_lane = ((uint32_t)(lid & 7) + (uint32_t)((lid >> 4) & 1) * 8) * ROWPADB
                          + (uint32_t)((lid >> 3) & 1) * 16
                          + (uint32_t)warp_col * 64 * ROWPADB;

    float acc[2][8][4];
#pragma unroll
    for (int m = 0; m < 2; m++)
#pragma unroll
        for (int nt = 0; nt < 8; nt++)
#pragma unroll
            for (int j = 0; j < 4; j++) acc[m][nt][j] = 0.f;

    // --- prologue: B[0] via cp.async into buffer 0; A[0] LDGs into registers
    {
#pragma unroll
        for (int u = 0; u < 4; u++) {
            int idx = tid + u * 256;
            int nn = idx >> 3, c8 = idx & 7;
            uint32_t doff = (uint32_t)nn * ROWPADB + (uint32_t)c8 * 16;
            uint32_t goff = (uint32_t)nn * DIM + (uint32_t)c8 * 8;  // t=0
            cp16(sbase + OFF_B + doff, g_w1t + goff);
        }
        cp_commit();
    }
    float4 va[8];
#pragma unroll
    for (int u = 0; u < 4; u++) {
        int idx = tid + u * 256;
        int r = idx >> 3, c8 = idx & 7;
        const float4* src = reinterpret_cast<const float4*>(
            x + (size_t)(rowBase + r) * DIM + c8 * 8);
        va[2 * u]     = __ldg(src);
        va[2 * u + 1] = __ldg(src + 1);
    }

    // B buffer index by t%3 (t = 0..7): 0,1,2,0,1,2,0,1
    for (int t = 0; t < 8; t++) {
        const uint32_t abuf = (t & 1) ? OFF_A1 : OFF_A0;
        const uint32_t bbuf = OFF_B + (uint32_t)(t % 3) * TILE_B;

        // --- convert prefetched A (fp32 -> fp16) into alternate A buffer
        //     (last reader of this buffer was compute(t-2), ordered before
        //      barrier(t-1), which every warp passed before arriving here)
#pragma unroll
        for (int u = 0; u < 4; u++) {
            int idx = tid + u * 256;
            int r = idx >> 3, c8 = idx & 7;
            float f[8] = {va[2 * u].x, va[2 * u].y, va[2 * u].z, va[2 * u].w,
                          va[2 * u + 1].x, va[2 * u + 1].y, va[2 * u + 1].z, va[2 * u + 1].w};
            uint32_t hp[4];
#pragma unroll
            for (int j = 0; j < 4; j++) {
                __half h0 = __float2half_rn(f[2 * j]);
                __half h1 = __float2half_rn(f[2 * j + 1]);
                hp[j] = (uint32_t)__half_as_ushort(h0) | ((uint32_t)__half_as_ushort(h1) << 16);
            }
            uint32_t off = (uint32_t)r * ROWPADB + (uint32_t)c8 * 16;
            *(uint4*)(bp + abuf + off) = make_uint4(hp[0], hp[1], hp[2], hp[3]);
        }

        // --- issue B[t+1] cp.async into buffer (t+1)%3 (reader compute(t-2)
        //     finished before barrier(t-1)); then wait for B[t]
        if (t < 7) {
            uint32_t nb = OFF_B + (uint32_t)((t + 1) % 3) * TILE_B;
#pragma unroll
            for (int u = 0; u < 4; u++) {
                int idx = tid + u * 256;
                int nn = idx >> 3, c8 = idx & 7;
                uint32_t doff = (uint32_t)nn * ROWPADB + (uint32_t)c8 * 16;
                uint32_t goff = (uint32_t)nn * DIM + (uint32_t)(t + 1) * KT + (uint32_t)c8 * 8;
                cp16(sbase + nb + doff, g_w1t + goff);
            }
            cp_commit();
            cp_wait<1>();                 // B[t] complete; B[t+1] may stay in flight
        } else {
            cp_wait<0>();
        }
        __syncthreads();                  // barrier(t): A[t] + B[t] visible to all

        // --- prefetch next A tile LDGs (latency hidden behind compute below)
        if (t < 7) {
#pragma unroll
            for (int u = 0; u < 4; u++) {
                int idx = tid + u * 256;
                int r = idx >> 3, c8 = idx & 7;
                const float4* src = reinterpret_cast<const float4*>(
                    x + (size_t)(rowBase + r) * DIM + (t + 1) * KT + c8 * 8);
                va[2 * u]     = __ldg(src);
                va[2 * u + 1] = __ldg(src + 1);
            }
        }

        // --- compute: 4 k-steps of 16, single pass
        const uint32_t bA = sbase + bbuf + b_lane - sbase; // b_lane is relative
        const uint32_t bAddr = sbase + (bbuf - 0) + b_lane;
        (void)bA;
#pragma unroll
        for (int ks = 0; ks < 4; ks++) {
            const uint32_t ko = (uint32_t)ks * 32;
            uint32_t a[2][4];
#pragma unroll
            for (int m = 0; m < 2; m++) ldsm_x4(a[m], aA[m] + abuf + ko);
#pragma unroll
            for (int ntp = 0; ntp < 4; ntp++) {
                const uint32_t no = (uint32_t)ntp * 16 * ROWPADB + ko;
                uint32_t bh[4];
                ldsm_x4(bh, bAddr + no);
#pragma unroll
                for (int m = 0; m < 2; m++) {
                    mma_f16(acc[m][2 * ntp],     a[m], bh);
                    mma_f16(acc[m][2 * ntp + 1], a[m], bh + 2);
                }
            }
        }
    }

    // --- epilogue: s = sum_col tanh(h + b1[col]) * W2[col], register-resident
    const int grp = lid >> 2;
    float p[2][2] = {{0.f, 0.f}, {0.f, 0.f}};
#pragma unroll
    for (int nt = 0; nt < 8; nt++) {
        int c0 = warp_col * 64 + nt * 8 + tig * 2;
        float b1a = __ldg(b1 + c0),     b1b = __ldg(b1 + c0 + 1);
        float w2a = __ldg(W2 + c0),     w2b = __ldg(W2 + c0 + 1);
#pragma unroll
        for (int m = 0; m < 2; m++) {
            p[m][0] += tanhf(acc[m][nt][0] + b1a) * w2a + tanhf(acc[m][nt][1] + b1b) * w2b;
            p[m][1] += tanhf(acc[m][nt][2] + b1a) * w2a + tanhf(acc[m][nt][3] + b1b) * w2b;
        }
    }
#pragma unroll
    for (int m = 0; m < 2; m++)
#pragma unroll
        for (int r = 0; r < 2; r++) {
            p[m][r] += __shfl_xor_sync(0xFFFFFFFF, p[m][r], 1);
            p[m][r] += __shfl_xor_sync(0xFFFFFFFF, p[m][r], 2);
        }
    if (tig == 0) {
#pragma unroll
        for (int m = 0; m < 2; m++)
#pragma unroll
            for (int r = 0; r < 2; r++) {
                int row = warp_row * 32 + m * 16 + r * 8 + grp;
                red[row * 2 + warp_col] = p[m][r];
            }
    }
    __syncthreads();
    if (tid < 128) {
        float s = red[tid * 2] + red[tid * 2 + 1] + __ldg(b2);
        e_sm[tid] = expf(s);             // no shift needed: |s| <= ~10, fp32-safe
    }
    __syncthreads();

    // --- scatter-pool: re-read this block's x tile (L2-hot, evict-first).
    // Thread owns dims (2*tid, 2*tid+1); rows sorted by segment -> few flushes.
    {
        const float2* xp = reinterpret_cast<const float2*>(x) + (size_t)rowBase * (DIM / 2) + tid;
        float a0 = 0.f, a1 = 0.f;
        int cur = seg_sm[0];
        for (int r = 0; r < 128; r += 4) {
            float2 v0 = __ldcs(xp + (size_t)(r + 0) * (DIM / 2));
            float2 v1 = __ldcs(xp + (size_t)(r + 1) * (DIM / 2));
            float2 v2 = __ldcs(xp + (size_t)(r + 2) * (DIM / 2));
            float2 v3 = __ldcs(xp + (size_t)(r + 3) * (DIM / 2));
            float2 vv[4] = {v0, v1, v2, v3};
#pragma unroll
            for (int j = 0; j < 4; j++) {
                int sg = seg_sm[r + j];
                if (sg != cur) {
                    atomicAdd(&g_num[(size_t)cur * DIM + 2 * tid],     a0);
                    atomicAdd(&g_num[(size_t)cur * DIM + 2 * tid + 1], a1);
                    a0 = 0.f; a1 = 0.f; cur = sg;
                }
                float e = e_sm[r + j];
                a0 += e * vv[j].x;
                a1 += e * vv[j].y;
            }
        }
        atomicAdd(&g_num[(size_t)cur * DIM + 2 * tid],     a0);
        atomicAdd(&g_num[(size_t)cur * DIM + 2 * tid + 1], a1);
    }
    if (tid == 0) {
        float d = 0.f;
        int cur = seg_sm[0];
        for (int r = 0; r < 128; r++) {
            int sg = seg_sm[r];
            if (sg != cur) { atomicAdd(&g_den[cur], d); d = 0.f; cur = sg; }
            d += e_sm[r];
        }
        atomicAdd(&g_den[cur], d);
    }
}

// ---------------------------------------------------------------------------
// Kernel 2 (finalize): out[b, d] = num[b, d] / (den[b] + 1e-8)
// ---------------------------------------------------------------------------
__global__ __launch_bounds__(256)
void finalize_kernel(float* __restrict__ out)
{
    const int b = blockIdx.x;
    const int tid = threadIdx.x;
    const float inv = 1.f / (g_den[b] + 1e-8f);
    float2 v = reinterpret_cast<const float2*>(g_num + (size_t)b * DIM)[tid];
    reinterpret_cast<float2*>(out + (size_t)b * DIM)[tid] =
        make_float2(v.x * inv, v.y * inv);
}

// ---------------------------------------------------------------------------
extern "C" void kernel_launch(void* const* d_in, const int* in_sizes, int n_in,
                              void* d_out, int out_size)
{
    const float* x     = (const float*)d_in[0];
    const void*  batch = (const void*)d_in[1];
    const float* W1    = (const float*)d_in[2];
    const float* b1    = (const float*)d_in[3];
    const float* W2    = (const float*)d_in[4];
    const float* b2    = (const float*)d_in[5];
    float*       out   = (float*)d_out;

    const int n = in_sizes[1];
    const int Bseg = out_size / DIM;

    cudaFuncSetAttribute(score_pool_kernel,
                         cudaFuncAttributeMaxDynamicSharedMemorySize, SMEM_REQ);

    prep_kernel<<<4 + ZBLK, 256>>>(Bseg, W1);
    score_pool_kernel<<<n / 128, 256, SMEM_REQ>>>(x, batch, n, b1, W2, b2);
    finalize_kernel<<<Bseg, 256>>>(out);
}